// round 2
// baseline (speedup 1.0000x reference)
#include <cuda_runtime.h>
#include <math.h>

#define BB 2
#define LL 1024
#define DIM 512
#define DSTATE 64
#define DCONV 4
#define DIN 2048
#define DTRANK 32
#define XDBL 160            // DT_RANK + 2*D_STATE
#define ROWS 2048           // B*L

// ---------------- scratch (device globals; no allocs allowed) ----------------
static __device__ __align__(16) float g_y   [ROWS * DIM];
static __device__ __align__(16) float g_xz  [ROWS * 2 * DIN];
static __device__ __align__(16) float g_u   [ROWS * DIN];
static __device__ __align__(16) float g_xdbl[ROWS * XDBL];
static __device__ __align__(16) float g_dt  [ROWS * DIN];
static __device__ __align__(16) float g_ys  [ROWS * DIN];
static __device__ __align__(16) float g_x2  [ROWS * DIM];
static __device__ __align__(16) float g_y2  [ROWS * DIM];
static __device__ __align__(16) float g_h1  [ROWS * DIN];
static __device__ __align__(16) float g_part[4 * ROWS * DIM];   // split-K partials (16MB)

// ---------------- helpers ----------------
__device__ __forceinline__ void fma2(unsigned long long& d, unsigned long long a, unsigned long long b) {
    asm("fma.rn.f32x2 %0, %1, %2, %0;" : "+l"(d) : "l"(a), "l"(b));
}
__device__ __forceinline__ float2 unpack2(unsigned long long v) {
    float2 r;
    asm("mov.b64 {%0, %1}, %2;" : "=f"(r.x), "=f"(r.y) : "l"(v));
    return r;
}
__device__ __forceinline__ float sigmoidf_(float x) { return __fdividef(1.f, 1.f + __expf(-x)); }
__device__ __forceinline__ float softplusf_(float x){ return x > 20.f ? x : log1pf(__expf(x)); }
__device__ __forceinline__ float geluf_(float x)    { return 0.5f * x * (1.f + erff(x * 0.70710678118654752f)); }

// ---------------- LayerNorm ----------------
__global__ void __launch_bounds__(128)
ln_kernel(const float* __restrict__ x, const float* __restrict__ g,
          const float* __restrict__ b, float* __restrict__ out, float eps)
{
    int row = blockIdx.x;
    const float* xr = x + (size_t)row * DIM;
    float v[4];
    float s = 0.f;
#pragma unroll
    for (int i = 0; i < 4; i++) { v[i] = xr[threadIdx.x + i * 128]; s += v[i]; }
    __shared__ float red[8];
#pragma unroll
    for (int o = 16; o > 0; o >>= 1) s += __shfl_xor_sync(0xffffffffu, s, o);
    if ((threadIdx.x & 31) == 0) red[threadIdx.x >> 5] = s;
    __syncthreads();
    float mean = (red[0] + red[1] + red[2] + red[3]) * (1.f / DIM);
    float s2 = 0.f;
#pragma unroll
    for (int i = 0; i < 4; i++) { float d = v[i] - mean; s2 += d * d; }
#pragma unroll
    for (int o = 16; o > 0; o >>= 1) s2 += __shfl_xor_sync(0xffffffffu, s2, o);
    if ((threadIdx.x & 31) == 0) red[4 + (threadIdx.x >> 5)] = s2;
    __syncthreads();
    float var = (red[4] + red[5] + red[6] + red[7]) * (1.f / DIM);
    float rstd = rsqrtf(var + eps);
#pragma unroll
    for (int i = 0; i < 4; i++) {
        int c = threadIdx.x + i * 128;
        out[(size_t)row * DIM + c] = (v[i] - mean) * rstd * g[c] + b[c];
    }
}

// ---------------- GEMM: C[M,N](+split-K part) = A[M,Ksl] @ W[N,Ksl]^T ----------------
// EPI: 0 none, 1 bias+softplus, 3 bias+gelu.  BM=128, BN=128, BK=8, 8x8/thread.
template<int EPI>
__global__ void __launch_bounds__(256, 2)
gemm_kernel(const float* __restrict__ A, int lda,
            const float* __restrict__ W, int Kw,
            float* __restrict__ C, int ldc,
            int N, int Ksl, size_t partStride,
            const float* __restrict__ bias)
{
    constexpr int BM = 128, BN = 128, BK = 8, TM = 8, TN = 8;
    __shared__ __align__(16) float As[BK][2 * BM];  // A duplicated: {a,a} pairs
    __shared__ __align__(16) float Bs[BK][BN];

    const int tid = threadIdx.x;
    const int m0 = blockIdx.y * BM;
    const int n0 = blockIdx.x * BN;
    const int lrow = tid >> 1;
    const int lseg = (tid & 1) * 4;
    const int tx = tid & 15;
    const int ty = tid >> 4;
    const size_t koff = (size_t)blockIdx.z * Ksl;

    const float* Ap = A + (size_t)(m0 + lrow) * lda + lseg + koff;
    const bool wval = (n0 + lrow) < N;
    const float* Wp = W + (size_t)(wval ? (n0 + lrow) : 0) * Kw + lseg + koff;
    C += (size_t)blockIdx.z * partStride;

    float4 av = *(const float4*)Ap;
    float4 wv = wval ? *(const float4*)Wp : make_float4(0, 0, 0, 0);

    unsigned long long acc[TM][TN / 2];
#pragma unroll
    for (int i = 0; i < TM; i++)
#pragma unroll
        for (int j = 0; j < TN / 2; j++) acc[i][j] = 0ull;

    int k0 = 0;
    while (true) {
        __syncthreads();
        *(float2*)&As[lseg + 0][2 * lrow] = make_float2(av.x, av.x);
        *(float2*)&As[lseg + 1][2 * lrow] = make_float2(av.y, av.y);
        *(float2*)&As[lseg + 2][2 * lrow] = make_float2(av.z, av.z);
        *(float2*)&As[lseg + 3][2 * lrow] = make_float2(av.w, av.w);
        Bs[lseg + 0][lrow] = wv.x;
        Bs[lseg + 1][lrow] = wv.y;
        Bs[lseg + 2][lrow] = wv.z;
        Bs[lseg + 3][lrow] = wv.w;
        __syncthreads();
        k0 += BK;
        if (k0 < Ksl) {
            av = *(const float4*)(Ap + k0);
            wv = wval ? *(const float4*)(Wp + k0) : make_float4(0, 0, 0, 0);
        }
#pragma unroll
        for (int kk = 0; kk < BK; kk++) {
            unsigned long long rm[TM];
#pragma unroll
            for (int q = 0; q < TM; q += 2) {
                ulonglong2 t = *(const ulonglong2*)&As[kk][2 * (ty * TM + q)];
                rm[q] = t.x; rm[q + 1] = t.y;
            }
            unsigned long long rn[TN / 2];
#pragma unroll
            for (int q = 0; q < TN / 2; q += 2) {
                ulonglong2 t = *(const ulonglong2*)&Bs[kk][tx * TN + 2 * q];
                rn[q] = t.x; rn[q + 1] = t.y;
            }
#pragma unroll
            for (int i = 0; i < TM; i++)
#pragma unroll
                for (int j = 0; j < TN / 2; j++)
                    fma2(acc[i][j], rm[i], rn[j]);
        }
        if (k0 >= Ksl) break;
    }

#pragma unroll
    for (int i = 0; i < TM; i++) {
        int m = m0 + ty * TM + i;
#pragma unroll
        for (int j = 0; j < TN / 2; j++) {
            int n = n0 + tx * TN + 2 * j;
            if (n < N) {   // N always even; pair never straddles the edge
                float2 v = unpack2(acc[i][j]);
                if (EPI == 1) {
                    v.x = softplusf_(v.x + bias[n]);
                    v.y = softplusf_(v.y + bias[n + 1]);
                } else if (EPI == 3) {
                    v.x = geluf_(v.x + bias[n]);
                    v.y = geluf_(v.y + bias[n + 1]);
                }
                C[(size_t)m * ldc + n]     = v.x;
                C[(size_t)m * ldc + n + 1] = v.y;
            }
        }
    }
}

// ---------------- split-K reduce (+epilogue). REPI: 0 sum, 2 sum+resid, 4 sum+bias+resid
template<int REPI>
__global__ void __launch_bounds__(256)
reduce_kernel(const float* __restrict__ part, float* __restrict__ out,
              int total4, int slices, size_t partStride, int ldc,
              const float* __restrict__ bias, const float* __restrict__ resid)
{
    int i = blockIdx.x * 256 + threadIdx.x;
    if (i >= total4) return;
    size_t e = (size_t)i * 4;
    float4 acc = *(const float4*)(part + e);
    for (int s = 1; s < slices; s++) {
        float4 v = *(const float4*)(part + (size_t)s * partStride + e);
        acc.x += v.x; acc.y += v.y; acc.z += v.z; acc.w += v.w;
    }
    if (REPI >= 4) {
        int n = (int)(e % ldc);
        acc.x += bias[n]; acc.y += bias[n + 1]; acc.z += bias[n + 2]; acc.w += bias[n + 3];
    }
    if (REPI >= 2) {
        float4 r = *(const float4*)(resid + e);
        acc.x += r.x; acc.y += r.y; acc.z += r.z; acc.w += r.w;
    }
    *(float4*)(out + e) = acc;
}

// ---------------- depthwise causal conv (D_CONV=4) + SiLU ----------------
__global__ void __launch_bounds__(256)
conv_silu_kernel(const float* __restrict__ cw, const float* __restrict__ cb)
{
    int gid = blockIdx.x * 256 + threadIdx.x;   // over ROWS*DIN
    int d = gid & (DIN - 1);
    int row = gid >> 11;                        // DIN = 2^11
    int t = row & (LL - 1);
    float acc = cb[d];
    const float* base = g_xz + (size_t)row * (2 * DIN) + d;
#pragma unroll
    for (int k = 0; k < DCONV; k++) {
        int off = k - (DCONV - 1);
        if (t + off >= 0)
            acc = fmaf(cw[d * DCONV + k], base[(long)off * (2 * DIN)], acc);
    }
    g_u[gid] = acc * sigmoidf_(acc);
}

// ---------------- selective scan: warp per (b,d) channel ----------------
#define GD 8     // d-channels (warps) per block
#define CT 32    // timestep chunk

__global__ void __launch_bounds__(256)
scan_kernel(const float* __restrict__ A_log, const float* __restrict__ Dw)
{
    __shared__ float sB[CT][DSTATE];
    __shared__ float sC[CT][DSTATE];
    __shared__ float sdt[CT][GD];
    __shared__ float su [CT][GD];
    __shared__ float sz [CT][GD];

    const int tid = threadIdx.x;
    const int w = tid >> 5, lane = tid & 31;
    const int b = blockIdx.y;
    const int d0 = blockIdx.x * GD;
    const int d = d0 + w;

    const float a0 = -__expf(A_log[d * DSTATE + lane]);
    const float a1 = -__expf(A_log[d * DSTATE + lane + 32]);
    const float Dd = Dw[d];
    float h0 = 0.f, h1 = 0.f;

    const float* xdbl_b = g_xdbl + (size_t)b * LL * XDBL;
    const float* dt_b = g_dt + (size_t)b * LL * DIN + d0;
    const float* u_b  = g_u  + (size_t)b * LL * DIN + d0;
    const float* z_b  = g_xz + (size_t)b * LL * (2 * DIN) + DIN + d0;
    float* ys_b = g_ys + (size_t)b * LL * DIN + d;

    for (int t0 = 0; t0 < LL; t0 += CT) {
        __syncthreads();
#pragma unroll
        for (int r = 0; r < (CT * DSTATE) / 256; r++) {   // 8
            int e = tid + r * 256;
            int tt = e >> 6, n = e & 63;
            const float* src = xdbl_b + (size_t)(t0 + tt) * XDBL + DTRANK;
            sB[tt][n] = src[n];
            sC[tt][n] = src[DSTATE + n];
        }
        {
            int tt = tid >> 3, dd = tid & 7;              // CT*GD = 256
            sdt[tt][dd] = dt_b[(size_t)(t0 + tt) * DIN + dd];
            su [tt][dd] = u_b [(size_t)(t0 + tt) * DIN + dd];
            sz [tt][dd] = z_b [(size_t)(t0 + tt) * (2 * DIN) + dd];
        }
        __syncthreads();
#pragma unroll 4
        for (int tt = 0; tt < CT; tt++) {
            float dtv = sdt[tt][w], uv = su[tt][w], zv = sz[tt][w];
            float dA0 = __expf(dtv * a0);
            float dA1 = __expf(dtv * a1);
            float du = dtv * uv;
            h0 = fmaf(dA0, h0, du * sB[tt][lane]);
            h1 = fmaf(dA1, h1, du * sB[tt][lane + 32]);
            float p = h0 * sC[tt][lane] + h1 * sC[tt][lane + 32];
#pragma unroll
            for (int o = 16; o > 0; o >>= 1)
                p += __shfl_xor_sync(0xffffffffu, p, o);
            if (lane == 0) {
                float yv = fmaf(uv, Dd, p);
                ys_b[(size_t)(t0 + tt) * DIN] = yv * (zv * sigmoidf_(zv));
            }
        }
    }
}

// ---------------- launch ----------------
extern "C" void kernel_launch(void* const* d_in, const int* in_sizes, int n_in,
                              void* d_out, int out_size)
{
    const float* x         = (const float*)d_in[0];
    const float* ln1_g     = (const float*)d_in[1];
    const float* ln1_b     = (const float*)d_in[2];
    const float* in_proj_w = (const float*)d_in[3];
    const float* conv_w    = (const float*)d_in[4];
    const float* conv_b    = (const float*)d_in[5];
    const float* x_proj_w  = (const float*)d_in[6];
    const float* dt_w      = (const float*)d_in[7];
    const float* dt_b      = (const float*)d_in[8];
    const float* A_log     = (const float*)d_in[9];
    const float* D         = (const float*)d_in[10];
    const float* out_proj_w= (const float*)d_in[11];
    const float* ln2_g     = (const float*)d_in[12];
    const float* ln2_b     = (const float*)d_in[13];
    const float* w1        = (const float*)d_in[14];
    const float* b1        = (const float*)d_in[15];
    const float* w2        = (const float*)d_in[16];
    const float* b2        = (const float*)d_in[17];
    float* out = (float*)d_out;

    float *y, *xz, *u, *xdbl, *dt, *ys, *x2, *y2, *h1, *part;
    cudaGetSymbolAddress((void**)&y,    g_y);
    cudaGetSymbolAddress((void**)&xz,   g_xz);
    cudaGetSymbolAddress((void**)&u,    g_u);
    cudaGetSymbolAddress((void**)&xdbl, g_xdbl);
    cudaGetSymbolAddress((void**)&dt,   g_dt);
    cudaGetSymbolAddress((void**)&ys,   g_ys);
    cudaGetSymbolAddress((void**)&x2,   g_x2);
    cudaGetSymbolAddress((void**)&y2,   g_y2);
    cudaGetSymbolAddress((void**)&h1,   g_h1);
    cudaGetSymbolAddress((void**)&part, g_part);

    // 1. LN1
    ln_kernel<<<ROWS, 128>>>(x, ln1_g, ln1_b, y, 1e-5f);

    // 2. in_proj: xz = y @ in_proj_w^T   [2048 x 4096], K=512
    gemm_kernel<0><<<dim3(32, 16, 1), 256>>>(y, DIM, in_proj_w, DIM, xz, 2 * DIN,
                                             2 * DIN, DIM, 0, nullptr);

    // 3. causal conv + silu -> u
    conv_silu_kernel<<<(ROWS * DIN) / 256, 256>>>(conv_w, conv_b);

    // 4. x_proj: xdbl = u @ x_proj_w^T  [2048 x 160], K=2048, split-K=8
    gemm_kernel<0><<<dim3(2, 16, 8), 256>>>(u, DIN, x_proj_w, DIN, part, XDBL,
                                            XDBL, DIN / 8, (size_t)ROWS * XDBL, nullptr);
    reduce_kernel<0><<<(ROWS * XDBL / 4 + 255) / 256, 256>>>(part, xdbl, ROWS * XDBL / 4, 8,
                                                             (size_t)ROWS * XDBL, XDBL, nullptr, nullptr);

    // 5. dt = softplus(xdbl[:, :32] @ dt_w^T + dt_b)  [2048 x 2048], K=32
    gemm_kernel<1><<<dim3(16, 16, 1), 256>>>(xdbl, XDBL, dt_w, DTRANK, dt, DIN,
                                             DIN, DTRANK, 0, dt_b);

    // 6. selective scan -> ys
    scan_kernel<<<dim3(DIN / GD, BB), 256>>>(A_log, D);

    // 7. out_proj: x2 = x + ys @ out_proj_w^T  [2048 x 512], K=2048, split-K=4
    gemm_kernel<0><<<dim3(4, 16, 4), 256>>>(ys, DIN, out_proj_w, DIN, part, DIM,
                                            DIM, DIN / 4, (size_t)ROWS * DIM, nullptr);
    reduce_kernel<2><<<(ROWS * DIM / 4 + 255) / 256, 256>>>(part, x2, ROWS * DIM / 4, 4,
                                                            (size_t)ROWS * DIM, DIM, nullptr, x);

    // 8. LN2
    ln_kernel<<<ROWS, 128>>>(x2, ln2_g, ln2_b, y2, 1e-6f);

    // 9. h1 = gelu(y2 @ w1^T + b1)  [2048 x 2048], K=512
    gemm_kernel<3><<<dim3(16, 16, 1), 256>>>(y2, DIM, w1, DIM, h1, 4 * DIM,
                                             4 * DIM, DIM, 0, b1);

    // 10. out = x2 + h1 @ w2^T + b2  [2048 x 512], K=2048, split-K=4
    gemm_kernel<0><<<dim3(4, 16, 4), 256>>>(h1, 4 * DIM, w2, 4 * DIM, part, DIM,
                                            DIM, DIN / 4, (size_t)ROWS * DIM, nullptr);
    reduce_kernel<4><<<(ROWS * DIM / 4 + 255) / 256, 256>>>(part, out, ROWS * DIM / 4, 4,
                                                            (size_t)ROWS * DIM, DIM, b2, x2);
}

// round 4
// speedup vs baseline: 1.5474x; 1.5474x over previous
#include <cuda_runtime.h>
#include <cuda_bf16.h>
#include <math.h>
#include <stdint.h>

#define BB 2
#define LL 1024
#define DIM 512
#define DSTATE 64
#define DCONV 4
#define DIN 2048
#define DTRANK 32
#define XDBL 160            // DT_RANK + 2*D_STATE
#define ROWS 2048           // B*L

// ---------------- scratch (device globals; no allocs allowed) ----------------
static __device__ __align__(16) float g_y   [ROWS * DIM];
static __device__ __align__(16) float g_xz  [ROWS * 2 * DIN];
static __device__ __align__(16) float g_u   [ROWS * DIN];
static __device__ __align__(16) float g_xdbl[ROWS * XDBL];
static __device__ __align__(16) float g_dt  [ROWS * DIN];
static __device__ __align__(16) float g_ys  [ROWS * DIN];
static __device__ __align__(16) float g_x2  [ROWS * DIM];
static __device__ __align__(16) float g_y2  [ROWS * DIM];
static __device__ __align__(16) float g_h1  [ROWS * DIN];
static __device__ __align__(16) float g_part[4 * ROWS * DIM];                    // split-K partials
static __device__ __align__(16) __nv_bfloat16 g_actb[ROWS * 6144];               // A' split-bf16
static __device__ __align__(16) __nv_bfloat16 g_wb  [4096 * 1536 + 512 * 6144]; // W' split-bf16

// ---------------- math helpers ----------------
__device__ __forceinline__ float sigmoidf_(float x) { return __fdividef(1.f, 1.f + __expf(-x)); }
__device__ __forceinline__ float softplusf_(float x){ return x > 20.f ? x : log1pf(__expf(x)); }
__device__ __forceinline__ float geluf_(float x)    { return 0.5f * x * (1.f + erff(x * 0.70710678118654752f)); }

// ---------------- PTX helpers (baseline ISA only: sm_80+, valid on sm_103) ----------------
__device__ __forceinline__ uint32_t smem_u32(const void* p) {
    uint32_t a;
    asm("{ .reg .u64 t; cvta.to.shared.u64 t, %1; cvt.u32.u64 %0, t; }" : "=r"(a) : "l"(p));
    return a;
}
__device__ __forceinline__ void cp16(uint32_t dst, const void* src, int srcsize) {
    asm volatile("cp.async.cg.shared.global [%0], [%1], 16, %2;" :: "r"(dst), "l"(src), "r"(srcsize) : "memory");
}
#define CP_COMMIT() asm volatile("cp.async.commit_group;" ::: "memory")
#define CP_WAIT1()  asm volatile("cp.async.wait_group 1;" ::: "memory")
#define CP_WAIT0()  asm volatile("cp.async.wait_group 0;" ::: "memory")

__device__ __forceinline__ void ldsm4(uint32_t& r0, uint32_t& r1, uint32_t& r2, uint32_t& r3, uint32_t addr) {
    asm volatile("ldmatrix.sync.aligned.m8n8.x4.shared.b16 {%0,%1,%2,%3}, [%4];"
                 : "=r"(r0), "=r"(r1), "=r"(r2), "=r"(r3) : "r"(addr));
}
__device__ __forceinline__ void mma16816(float* c, const uint32_t* a, const uint32_t* b) {
    asm volatile("mma.sync.aligned.m16n8k16.row.col.f32.bf16.bf16.f32 "
                 "{%0,%1,%2,%3}, {%4,%5,%6,%7}, {%8,%9}, {%0,%1,%2,%3};"
                 : "+f"(c[0]), "+f"(c[1]), "+f"(c[2]), "+f"(c[3])
                 : "r"(a[0]), "r"(a[1]), "r"(a[2]), "r"(a[3]), "r"(b[0]), "r"(b[1]));
}

// ---------------- LayerNorm ----------------
__global__ void __launch_bounds__(128)
ln_kernel(const float* __restrict__ x, const float* __restrict__ g,
          const float* __restrict__ b, float* __restrict__ out, float eps)
{
    int row = blockIdx.x;
    const float* xr = x + (size_t)row * DIM;
    float v[4];
    float s = 0.f;
#pragma unroll
    for (int i = 0; i < 4; i++) { v[i] = xr[threadIdx.x + i * 128]; s += v[i]; }
    __shared__ float red[8];
#pragma unroll
    for (int o = 16; o > 0; o >>= 1) s += __shfl_xor_sync(0xffffffffu, s, o);
    if ((threadIdx.x & 31) == 0) red[threadIdx.x >> 5] = s;
    __syncthreads();
    float mean = (red[0] + red[1] + red[2] + red[3]) * (1.f / DIM);
    float s2 = 0.f;
#pragma unroll
    for (int i = 0; i < 4; i++) { float d = v[i] - mean; s2 += d * d; }
#pragma unroll
    for (int o = 16; o > 0; o >>= 1) s2 += __shfl_xor_sync(0xffffffffu, s2, o);
    if ((threadIdx.x & 31) == 0) red[4 + (threadIdx.x >> 5)] = s2;
    __syncthreads();
    float var = (red[4] + red[5] + red[6] + red[7]) * (1.f / DIM);
    float rstd = rsqrtf(var + eps);
#pragma unroll
    for (int i = 0; i < 4; i++) {
        int c = threadIdx.x + i * 128;
        out[(size_t)row * DIM + c] = (v[i] - mean) * rstd * g[c] + b[c];
    }
}

// ---------------- fp32 -> split-bf16 (3-plane) conversion ----------------
// mode 0 (activation): dst cols [0,K)=hi, [K,2K)=lo, [2K,3K)=hi
// mode 1 (weight):     dst cols [0,K)=hi, [K,2K)=hi, [2K,3K)=lo
__global__ void __launch_bounds__(256)
cvt_split(const float* __restrict__ src, int lda, int K, int K3p, int rows,
          __nv_bfloat16* __restrict__ dst, int mode)
{
    int i = blockIdx.x * 256 + threadIdx.x;
    if (i >= rows * K) return;
    int r = i / K, k = i - r * K;
    float a = src[(size_t)r * lda + k];
    __nv_bfloat16 hi = __float2bfloat16(a);
    __nv_bfloat16 lo = __float2bfloat16(a - __bfloat162float(hi));
    __nv_bfloat16* dr = dst + (size_t)r * K3p;
    if (mode == 0) { dr[k] = hi; dr[K + k] = lo;  dr[2 * K + k] = hi; }
    else           { dr[k] = hi; dr[K + k] = hi;  dr[2 * K + k] = lo; }
}

__global__ void __launch_bounds__(256)
pad_zero(__nv_bfloat16* __restrict__ dst, int K3p, int k0, int rows)
{
    int pad = K3p - k0;
    int i = blockIdx.x * 256 + threadIdx.x;
    if (i >= rows * pad) return;
    int r = i / pad, k = i - r * pad;
    dst[(size_t)r * K3p + k0 + k] = __float2bfloat16(0.f);
}

// ---------------- HMMA GEMM: C[M,N] = A'[M,K3] @ W'[N,K3]^T ----------------
// BM=128, BN=64, BK=32 bf16. 256 threads, warp grid 4(m)x2(n), warp tile 32x32.
// EPI: 0 none, 1 bias+softplus, 3 bias+gelu  (split-K epilogues live in reduce)
#define APITCH 80   // 32 bf16 (64B) + 16B pad -> conflict-free ldmatrix
template<int EPI>
__global__ void __launch_bounds__(256)
hmma_gemm(const __nv_bfloat16* __restrict__ A, const __nv_bfloat16* __restrict__ W,
          float* __restrict__ C, int N, int K3, int Ksl, size_t partStride,
          const float* __restrict__ bias)
{
    __shared__ __align__(16) char smA[2][128 * APITCH];
    __shared__ __align__(16) char smB[2][64 * APITCH];

    const int tid = threadIdx.x;
    const int lane = tid & 31, wid = tid >> 5;
    const int warpM = (wid & 3) * 32;     // 4 warps along M
    const int warpN = (wid >> 2) * 32;    // 2 warps along N
    const int m0 = blockIdx.y * 128;
    const int n0 = blockIdx.x * 64;
    const int koff = blockIdx.z * Ksl;
    const int NC = Ksl / 32;
    C += (size_t)blockIdx.z * partStride;

    const uint32_t aBase[2] = { smem_u32(smA[0]), smem_u32(smA[1]) };
    const uint32_t bBase[2] = { smem_u32(smB[0]), smem_u32(smB[1]) };

    // per-thread load coords
    const int lr = tid >> 2, lseg = tid & 3;

    // ldmatrix addresses (lane-dependent)
    const uint32_t aLdOff = (uint32_t)((warpM + (lane & 15)) * APITCH + (lane >> 4) * 16);
    const uint32_t bLdOff = (uint32_t)((warpN + (lane & 7)) * APITCH + (lane >> 3) * 16);

    float acc[2][4][4];
#pragma unroll
    for (int i = 0; i < 2; i++)
#pragma unroll
        for (int j = 0; j < 4; j++)
#pragma unroll
            for (int q = 0; q < 4; q++) acc[i][j][q] = 0.f;

    // ---- load chunk c into buffer buf ----
    auto load_chunk = [&](int buf, int c) {
        const __nv_bfloat16* asrc = A + (size_t)(m0 + lr) * K3 + koff + c * 32 + lseg * 8;
        cp16(aBase[buf] + (uint32_t)(lr * APITCH + lseg * 16), asrc, 16);
        const __nv_bfloat16* asrc2 = asrc + (size_t)64 * K3;
        cp16(aBase[buf] + (uint32_t)((lr + 64) * APITCH + lseg * 16), asrc2, 16);
        int brow = n0 + lr;
        bool bv = (brow < N) && (lr < 64);
        const __nv_bfloat16* bsrc = W + (size_t)(bv ? brow : 0) * K3 + koff + c * 32 + lseg * 8;
        if (lr < 64) cp16(bBase[buf] + (uint32_t)(lr * APITCH + lseg * 16), bsrc, bv ? 16 : 0);
    };

    load_chunk(0, 0);
    CP_COMMIT();

    for (int c = 0; c < NC; c++) {
        const int buf = c & 1;
        if (c + 1 < NC) {
            load_chunk(buf ^ 1, c + 1);
            CP_COMMIT();
            CP_WAIT1();
        } else {
            CP_WAIT0();
        }
        __syncthreads();

        uint32_t aF[2][2][4];   // [mt][kh][4]
#pragma unroll
        for (int mt = 0; mt < 2; mt++)
#pragma unroll
            for (int kh = 0; kh < 2; kh++)
                ldsm4(aF[mt][kh][0], aF[mt][kh][1], aF[mt][kh][2], aF[mt][kh][3],
                      aBase[buf] + aLdOff + (uint32_t)(mt * 16 * APITCH + kh * 32));
        uint32_t bF[4][4];      // [nt][{b0h0,b1h0,b0h1,b1h1}]
#pragma unroll
        for (int nt = 0; nt < 4; nt++)
            ldsm4(bF[nt][0], bF[nt][1], bF[nt][2], bF[nt][3],
                  bBase[buf] + bLdOff + (uint32_t)(nt * 8 * APITCH));
#pragma unroll
        for (int kh = 0; kh < 2; kh++)
#pragma unroll
            for (int mt = 0; mt < 2; mt++)
#pragma unroll
                for (int nt = 0; nt < 4; nt++)
                    mma16816(acc[mt][nt], aF[mt][kh], &bF[nt][kh * 2]);
        __syncthreads();
    }

    // ---- epilogue: direct f32 stores (float2 pairs) ----
#pragma unroll
    for (int mt = 0; mt < 2; mt++) {
        int row = m0 + warpM + mt * 16 + (lane >> 2);
#pragma unroll
        for (int nt = 0; nt < 4; nt++) {
            int col = n0 + warpN + nt * 8 + 2 * (lane & 3);
            if (col < N) {
                float v0 = acc[mt][nt][0], v1 = acc[mt][nt][1];
                float v2 = acc[mt][nt][2], v3 = acc[mt][nt][3];
                if (EPI == 1) {
                    float b0 = bias[col], b1 = bias[col + 1];
                    v0 = softplusf_(v0 + b0); v1 = softplusf_(v1 + b1);
                    v2 = softplusf_(v2 + b0); v3 = softplusf_(v3 + b1);
                } else if (EPI == 3) {
                    float b0 = bias[col], b1 = bias[col + 1];
                    v0 = geluf_(v0 + b0); v1 = geluf_(v1 + b1);
                    v2 = geluf_(v2 + b0); v3 = geluf_(v3 + b1);
                }
                *(float2*)&C[(size_t)row * N + col]       = make_float2(v0, v1);
                *(float2*)&C[(size_t)(row + 8) * N + col] = make_float2(v2, v3);
            }
        }
    }
}

// ---------------- split-K reduce (+epilogue). REPI: 0 sum, 2 sum+resid, 4 sum+bias+resid
template<int REPI>
__global__ void __launch_bounds__(256)
reduce_kernel(const float* __restrict__ part, float* __restrict__ out,
              int total4, int slices, size_t partStride, int ldc,
              const float* __restrict__ bias, const float* __restrict__ resid)
{
    int i = blockIdx.x * 256 + threadIdx.x;
    if (i >= total4) return;
    size_t e = (size_t)i * 4;
    float4 acc = *(const float4*)(part + e);
    for (int s = 1; s < slices; s++) {
        float4 v = *(const float4*)(part + (size_t)s * partStride + e);
        acc.x += v.x; acc.y += v.y; acc.z += v.z; acc.w += v.w;
    }
    if (REPI >= 4) {
        int n = (int)(e % ldc);
        acc.x += bias[n]; acc.y += bias[n + 1]; acc.z += bias[n + 2]; acc.w += bias[n + 3];
    }
    if (REPI >= 2) {
        float4 r = *(const float4*)(resid + e);
        acc.x += r.x; acc.y += r.y; acc.z += r.z; acc.w += r.w;
    }
    *(float4*)(out + e) = acc;
}

// ---------------- depthwise causal conv (D_CONV=4) + SiLU ----------------
__global__ void __launch_bounds__(256)
conv_silu_kernel(const float* __restrict__ cw, const float* __restrict__ cb)
{
    int gid = blockIdx.x * 256 + threadIdx.x;   // over ROWS*DIN
    int d = gid & (DIN - 1);
    int row = gid >> 11;
    int t = row & (LL - 1);
    float acc = cb[d];
    const float* base = g_xz + (size_t)row * (2 * DIN) + d;
#pragma unroll
    for (int k = 0; k < DCONV; k++) {
        int off = k - (DCONV - 1);
        if (t + off >= 0)
            acc = fmaf(cw[d * DCONV + k], base[(long)off * (2 * DIN)], acc);
    }
    g_u[gid] = acc * sigmoidf_(acc);
}

// ---------------- selective scan: warp per (b,d) channel ----------------
#define GD 8
#define CT 32

__global__ void __launch_bounds__(256)
scan_kernel(const float* __restrict__ A_log, const float* __restrict__ Dw)
{
    __shared__ float sB[CT][DSTATE];
    __shared__ float sC[CT][DSTATE];
    __shared__ float sdt[CT][GD];
    __shared__ float su [CT][GD];
    __shared__ float sz [CT][GD];

    const int tid = threadIdx.x;
    const int w = tid >> 5, lane = tid & 31;
    const int b = blockIdx.y;
    const int d0 = blockIdx.x * GD;
    const int d = d0 + w;

    const float a0 = -__expf(A_log[d * DSTATE + lane]);
    const float a1 = -__expf(A_log[d * DSTATE + lane + 32]);
    const float Dd = Dw[d];
    float h0 = 0.f, h1 = 0.f;

    const float* xdbl_b = g_xdbl + (size_t)b * LL * XDBL;
    const float* dt_b = g_dt + (size_t)b * LL * DIN + d0;
    const float* u_b  = g_u  + (size_t)b * LL * DIN + d0;
    const float* z_b  = g_xz + (size_t)b * LL * (2 * DIN) + DIN + d0;
    float* ys_b = g_ys + (size_t)b * LL * DIN + d;

    for (int t0 = 0; t0 < LL; t0 += CT) {
        __syncthreads();
#pragma unroll
        for (int r = 0; r < (CT * DSTATE) / 256; r++) {
            int e = tid + r * 256;
            int tt = e >> 6, n = e & 63;
            const float* src = xdbl_b + (size_t)(t0 + tt) * XDBL + DTRANK;
            sB[tt][n] = src[n];
            sC[tt][n] = src[DSTATE + n];
        }
        {
            int tt = tid >> 3, dd = tid & 7;
            sdt[tt][dd] = dt_b[(size_t)(t0 + tt) * DIN + dd];
            su [tt][dd] = u_b [(size_t)(t0 + tt) * DIN + dd];
            sz [tt][dd] = z_b [(size_t)(t0 + tt) * (2 * DIN) + dd];
        }
        __syncthreads();
#pragma unroll 4
        for (int tt = 0; tt < CT; tt++) {
            float dtv = sdt[tt][w], uv = su[tt][w], zv = sz[tt][w];
            float dA0 = __expf(dtv * a0);
            float dA1 = __expf(dtv * a1);
            float du = dtv * uv;
            h0 = fmaf(dA0, h0, du * sB[tt][lane]);
            h1 = fmaf(dA1, h1, du * sB[tt][lane + 32]);
            float p = h0 * sC[tt][lane] + h1 * sC[tt][lane + 32];
#pragma unroll
            for (int o = 16; o > 0; o >>= 1)
                p += __shfl_xor_sync(0xffffffffu, p, o);
            if (lane == 0) {
                float yv = fmaf(uv, Dd, p);
                ys_b[(size_t)(t0 + tt) * DIN] = yv * (zv * sigmoidf_(zv));
            }
        }
    }
}

// ---------------- launch ----------------
static inline int cdiv(int a, int b) { return (a + b - 1) / b; }

extern "C" void kernel_launch(void* const* d_in, const int* in_sizes, int n_in,
                              void* d_out, int out_size)
{
    const float* x         = (const float*)d_in[0];
    const float* ln1_g     = (const float*)d_in[1];
    const float* ln1_b     = (const float*)d_in[2];
    const float* in_proj_w = (const float*)d_in[3];
    const float* conv_w    = (const float*)d_in[4];
    const float* conv_b    = (const float*)d_in[5];
    const float* x_proj_w  = (const float*)d_in[6];
    const float* dt_w      = (const float*)d_in[7];
    const float* dt_b      = (const float*)d_in[8];
    const float* A_log     = (const float*)d_in[9];
    const float* D         = (const float*)d_in[10];
    const float* out_proj_w= (const float*)d_in[11];
    const float* ln2_g     = (const float*)d_in[12];
    const float* ln2_b     = (const float*)d_in[13];
    const float* w1        = (const float*)d_in[14];
    const float* b1        = (const float*)d_in[15];
    const float* w2        = (const float*)d_in[16];
    const float* b2        = (const float*)d_in[17];
    float* out = (float*)d_out;

    float *y, *xz, *u, *xdbl, *dt, *ys, *x2, *y2, *h1, *part;
    __nv_bfloat16 *actb, *wb;
    cudaGetSymbolAddress((void**)&y,    g_y);
    cudaGetSymbolAddress((void**)&xz,   g_xz);
    cudaGetSymbolAddress((void**)&u,    g_u);
    cudaGetSymbolAddress((void**)&xdbl, g_xdbl);
    cudaGetSymbolAddress((void**)&dt,   g_dt);
    cudaGetSymbolAddress((void**)&ys,   g_ys);
    cudaGetSymbolAddress((void**)&x2,   g_x2);
    cudaGetSymbolAddress((void**)&y2,   g_y2);
    cudaGetSymbolAddress((void**)&h1,   g_h1);
    cudaGetSymbolAddress((void**)&part, g_part);
    cudaGetSymbolAddress((void**)&actb, g_actb);
    cudaGetSymbolAddress((void**)&wb,   g_wb);

    // 1. LN1
    ln_kernel<<<ROWS, 128>>>(x, ln1_g, ln1_b, y, 1e-5f);

    // 2. in_proj: xz = y @ in_proj_w^T  [2048 x 4096], K=512 -> K3=1536
    cvt_split<<<cdiv(ROWS * DIM, 256), 256>>>(y, DIM, DIM, 1536, ROWS, actb, 0);
    cvt_split<<<cdiv(4096 * DIM, 256), 256>>>(in_proj_w, DIM, DIM, 1536, 4096, wb, 1);
    hmma_gemm<0><<<dim3(64, 16, 1), 256>>>(actb, wb, xz, 2 * DIN, 1536, 1536, 0, nullptr);

    // 3. causal conv + silu -> u
    conv_silu_kernel<<<(ROWS * DIN) / 256, 256>>>(conv_w, conv_b);

    // 4. x_proj: xdbl = u @ x_proj_w^T  [2048 x 160], K=2048 -> K3=6144, split-K=4
    cvt_split<<<cdiv(ROWS * DIN, 256), 256>>>(u, DIN, DIN, 6144, ROWS, actb, 0);
    cvt_split<<<cdiv(XDBL * DIN, 256), 256>>>(x_proj_w, DIN, DIN, 6144, XDBL, wb, 1);
    hmma_gemm<0><<<dim3(3, 16, 4), 256>>>(actb, wb, part, XDBL, 6144, 1536,
                                          (size_t)ROWS * XDBL, nullptr);
    reduce_kernel<0><<<(ROWS * XDBL / 4 + 255) / 256, 256>>>(part, xdbl, ROWS * XDBL / 4, 4,
                                                             (size_t)ROWS * XDBL, XDBL, nullptr, nullptr);

    // 5. dt = softplus(xdbl[:, :32] @ dt_w^T + dt_b)  [2048 x 2048], K=32 -> K3=96 pad 128
    cvt_split<<<cdiv(ROWS * DTRANK, 256), 256>>>(xdbl, XDBL, DTRANK, 128, ROWS, actb, 0);
    cvt_split<<<cdiv(DIN * DTRANK, 256), 256>>>(dt_w, DTRANK, DTRANK, 128, DIN, wb, 1);
    pad_zero<<<cdiv(ROWS * 32, 256), 256>>>(actb, 128, 96, ROWS);
    pad_zero<<<cdiv(DIN * 32, 256), 256>>>(wb, 128, 96, DIN);
    hmma_gemm<1><<<dim3(32, 16, 1), 256>>>(actb, wb, dt, DIN, 128, 128, 0, dt_b);

    // 6. selective scan -> ys
    scan_kernel<<<dim3(DIN / GD, BB), 256>>>(A_log, D);

    // 7. out_proj: x2 = x + ys @ out_proj_w^T  [2048 x 512], K=2048 -> K3=6144, split-K=2
    cvt_split<<<cdiv(ROWS * DIN, 256), 256>>>(ys, DIN, DIN, 6144, ROWS, actb, 0);
    cvt_split<<<cdiv(DIM * DIN, 256), 256>>>(out_proj_w, DIN, DIN, 6144, DIM, wb, 1);
    hmma_gemm<0><<<dim3(8, 16, 2), 256>>>(actb, wb, part, DIM, 6144, 3072,
                                          (size_t)ROWS * DIM, nullptr);
    reduce_kernel<2><<<(ROWS * DIM / 4 + 255) / 256, 256>>>(part, x2, ROWS * DIM / 4, 2,
                                                            (size_t)ROWS * DIM, DIM, nullptr, x);

    // 8. LN2
    ln_kernel<<<ROWS, 128>>>(x2, ln2_g, ln2_b, y2, 1e-6f);

    // 9. h1 = gelu(y2 @ w1^T + b1)  [2048 x 2048], K=512 -> K3=1536
    cvt_split<<<cdiv(ROWS * DIM, 256), 256>>>(y2, DIM, DIM, 1536, ROWS, actb, 0);
    cvt_split<<<cdiv(4 * DIM * DIM, 256), 256>>>(w1, DIM, DIM, 1536, 4 * DIM, wb, 1);
    hmma_gemm<3><<<dim3(32, 16, 1), 256>>>(actb, wb, h1, 4 * DIM, 1536, 1536, 0, b1);

    // 10. out = x2 + h1 @ w2^T + b2  [2048 x 512], K=2048 -> K3=6144, split-K=2
    cvt_split<<<cdiv(ROWS * DIN, 256), 256>>>(h1, DIN, DIN, 6144, ROWS, actb, 0);
    cvt_split<<<cdiv(DIM * DIN, 256), 256>>>(w2, DIN, DIN, 6144, DIM, wb, 1);
    hmma_gemm<0><<<dim3(8, 16, 2), 256>>>(actb, wb, part, DIM, 6144, 3072,
                                          (size_t)ROWS * DIM, nullptr);
    reduce_kernel<4><<<(ROWS * DIM / 4 + 255) / 256, 256>>>(part, out, ROWS * DIM / 4, 2,
                                                            (size_t)ROWS * DIM, DIM, b2, x2);
}